// round 2
// baseline (speedup 1.0000x reference)
#include <cuda_runtime.h>
#include <math.h>

#define BATCH   4096
#define DIMN    256
#define FPC_    8
#define NBLK    (BATCH / FPC_)          // 512
#define PPB     28                      // pairs per block (8 choose 2)
#define NPAIRS  (NBLK * PPB)            // 14336
#define TILE    64
#define NJT     (BATCH / TILE)          // 64 j-tiles
#define KC      16
#define SHIFT   20.0f

// ---- scratch (no allocations allowed; device globals) ----
__device__ float g_norm[BATCH];
__device__ float g_Spart[NJT * BATCH];  // [jtile][row] partial exp-sums
__device__ float g_LSE[BATCH];
__device__ float g_pairsum[NBLK];

__constant__ int c_pa[PPB] = {0,0,0,0,0,0,0,1,1,1,1,1,1,2,2,2,2,2,3,3,3,3,4,4,4,5,5,6};
__constant__ int c_pb[PPB] = {1,2,3,4,5,6,7,2,3,4,5,6,7,3,4,5,6,7,4,5,6,7,5,6,7,6,7,7};

// ---------------------------------------------------------------------------
// K1: squared row norms. 8 warps/block, 1 warp per row, lane loads 8 floats.
// ---------------------------------------------------------------------------
__global__ void norms_kernel(const float* __restrict__ x) {
    int warp = threadIdx.x >> 5;
    int lane = threadIdx.x & 31;
    int row  = blockIdx.x * 8 + warp;
    const float4* xr = (const float4*)(x + (size_t)row * DIMN);
    float4 a = xr[lane * 2];
    float4 b = xr[lane * 2 + 1];
    float s = a.x*a.x + a.y*a.y + a.z*a.z + a.w*a.w
            + b.x*b.x + b.y*b.y + b.z*b.z + b.w*b.w;
    #pragma unroll
    for (int o = 16; o; o >>= 1) s += __shfl_down_sync(0xffffffffu, s, o);
    if (lane == 0) g_norm[row] = s;
}

// ---------------------------------------------------------------------------
// K2: fused Gram-tile + distance + masked exp + per-row partial sum.
// 64x64 tile per block, 256 threads (16x16), 4x4 microtile per thread.
// Writes g_Spart[blockIdx.x * BATCH + row] = sum_j-in-tile exp(d - SHIFT)
// with in-block (same group of 8) columns masked to 0.
// ---------------------------------------------------------------------------
__global__ void __launch_bounds__(256) distexp_kernel(const float* __restrict__ x) {
    __shared__ float As[KC][TILE];
    __shared__ float Bs[KC][TILE];
    __shared__ float red[TILE][17];

    const int tid = threadIdx.x;
    const int tx = tid & 15, ty = tid >> 4;
    const int rowBase = blockIdx.y * TILE;
    const int colBase = blockIdx.x * TILE;

    float acc[4][4] = {};

    const int lr = tid >> 2;           // local row 0..63 for loading
    const int lk = (tid & 3) * 4;      // k offset 0,4,8,12

    const float* pa = x + (size_t)(rowBase + lr) * DIMN + lk;
    const float* pb = x + (size_t)(colBase + lr) * DIMN + lk;

    for (int kc = 0; kc < DIMN; kc += KC) {
        float4 av = *(const float4*)(pa + kc);
        float4 bv = *(const float4*)(pb + kc);
        __syncthreads();  // protect previous iteration's reads
        As[lk + 0][lr] = av.x; As[lk + 1][lr] = av.y;
        As[lk + 2][lr] = av.z; As[lk + 3][lr] = av.w;
        Bs[lk + 0][lr] = bv.x; Bs[lk + 1][lr] = bv.y;
        Bs[lk + 2][lr] = bv.z; Bs[lk + 3][lr] = bv.w;
        __syncthreads();
        #pragma unroll
        for (int k = 0; k < KC; k++) {
            float a0 = As[k][ty*4+0], a1 = As[k][ty*4+1];
            float a2 = As[k][ty*4+2], a3 = As[k][ty*4+3];
            float b0 = Bs[k][tx*4+0], b1 = Bs[k][tx*4+1];
            float b2 = Bs[k][tx*4+2], b3 = Bs[k][tx*4+3];
            acc[0][0] += a0*b0; acc[0][1] += a0*b1; acc[0][2] += a0*b2; acc[0][3] += a0*b3;
            acc[1][0] += a1*b0; acc[1][1] += a1*b1; acc[1][2] += a1*b2; acc[1][3] += a1*b3;
            acc[2][0] += a2*b0; acc[2][1] += a2*b1; acc[2][2] += a2*b2; acc[2][3] += a2*b3;
            acc[3][0] += a3*b0; acc[3][1] += a3*b1; acc[3][2] += a3*b2; acc[3][3] += a3*b3;
        }
    }

    // epilogue: distances -> masked exp -> per-thread row sums
    const int r0 = rowBase + ty * 4;
    const int c0 = colBase + tx * 4;
    float nj[4];
    #pragma unroll
    for (int j = 0; j < 4; j++) nj[j] = g_norm[c0 + j];

    float rs[4];
    #pragma unroll
    for (int i = 0; i < 4; i++) {
        const int gr = r0 + i;
        const float ni = g_norm[gr];
        const int rb = gr >> 3;
        float s = 0.f;
        #pragma unroll
        for (int j = 0; j < 4; j++) {
            float d2 = ni + nj[j] - 2.0f * acc[i][j];
            float d  = sqrtf(fmaxf(d2, 0.0f));
            float e  = __expf(d - SHIFT);
            bool same = (((c0 + j) >> 3) == rb);
            s += same ? 0.0f : e;
        }
        rs[i] = s;
    }

    __syncthreads();
    #pragma unroll
    for (int i = 0; i < 4; i++) red[ty * 4 + i][tx] = rs[i];
    __syncthreads();

    if (tid < TILE) {
        float s = 0.f;
        #pragma unroll
        for (int j = 0; j < 16; j++) s += red[tid][j];
        g_Spart[(size_t)blockIdx.x * BATCH + rowBase + tid] = s;
    }
}

// ---------------------------------------------------------------------------
// K3: per-row LSE_out = log(sum over j-tiles) + SHIFT. Deterministic order.
// ---------------------------------------------------------------------------
__global__ void lse_kernel() {
    int r = blockIdx.x * blockDim.x + threadIdx.x;
    float s = 0.f;
    #pragma unroll
    for (int jt = 0; jt < NJT; jt++) s += g_Spart[(size_t)jt * BATCH + r];
    g_LSE[r] = logf(s) + SHIFT;
}

// ---------------------------------------------------------------------------
// K4: per 8-block: recompute the 28 in-block distances directly from x,
//     loss(p) = log1p(exp(LSE_out[anchor] - d)), deterministic block sum.
// ---------------------------------------------------------------------------
__global__ void __launch_bounds__(256) pair_kernel(const float* __restrict__ x) {
    __shared__ float xs[FPC_ * DIMN];
    __shared__ float pl[PPB];
    const int blk = blockIdx.x;
    const int tid = threadIdx.x;

    // load 8 rows (2048 floats) via float4
    const float4* src = (const float4*)(x + (size_t)blk * FPC_ * DIMN);
    float4* dst = (float4*)xs;
    dst[tid]       = src[tid];
    dst[tid + 256] = src[tid + 256];
    __syncthreads();

    const int warp = tid >> 5, lane = tid & 31;
    for (int p = warp; p < PPB; p += 8) {
        const int a = c_pa[p], b = c_pb[p];
        const float* xa = xs + a * DIMN;
        const float* xb = xs + b * DIMN;
        float dot = 0.f;
        #pragma unroll
        for (int k = 0; k < DIMN / 32; k++)
            dot += xa[lane + 32 * k] * xb[lane + 32 * k];
        #pragma unroll
        for (int o = 16; o; o >>= 1) dot += __shfl_down_sync(0xffffffffu, dot, o);
        if (lane == 0) {
            int ga = blk * FPC_ + a, gb = blk * FPC_ + b;
            float d2 = g_norm[ga] + g_norm[gb] - 2.0f * dot;
            float d  = sqrtf(fmaxf(d2, 0.0f));
            float z  = g_LSE[ga] - d;            // anchor is the smaller index
            float loss = (z > 20.0f) ? z : log1pf(expf(z));
            pl[p] = loss;
        }
    }
    __syncthreads();
    if (tid == 0) {
        float s = 0.f;
        #pragma unroll
        for (int p = 0; p < PPB; p++) s += pl[p];
        g_pairsum[blk] = s;
    }
}

// ---------------------------------------------------------------------------
// K5: final deterministic mean over 512 block sums.
// ---------------------------------------------------------------------------
__global__ void final_kernel(float* __restrict__ out) {
    __shared__ float sm[NBLK];
    sm[threadIdx.x] = g_pairsum[threadIdx.x];
    __syncthreads();
    #pragma unroll
    for (int s = NBLK / 2; s > 0; s >>= 1) {
        if (threadIdx.x < s) sm[threadIdx.x] += sm[threadIdx.x + s];
        __syncthreads();
    }
    if (threadIdx.x == 0) out[0] = sm[0] / (float)NPAIRS;
}

// ---------------------------------------------------------------------------
extern "C" void kernel_launch(void* const* d_in, const int* in_sizes, int n_in,
                              void* d_out, int out_size) {
    const float* x = (const float*)d_in[0];
    float* out = (float*)d_out;

    norms_kernel<<<BATCH / 8, 256>>>(x);
    dim3 grid2(NJT, NJT);
    distexp_kernel<<<grid2, 256>>>(x);
    lse_kernel<<<BATCH / 256, 256>>>();
    pair_kernel<<<NBLK, 256>>>(x);
    final_kernel<<<1, NBLK>>>(out);
}

// round 6
// speedup vs baseline: 3.3580x; 3.3580x over previous
#include <cuda_runtime.h>
#include <cuda_bf16.h>
#include <cstdint>
#include <math.h>

#define BATCH   4096
#define DIMN    256
#define FPC_    8
#define NBLK    (BATCH / FPC_)          // 512
#define PPB     28
#define NPAIRS  (NBLK * PPB)            // 14336
#define MT      128
#define NT      128
#define NJT     (BATCH / NT)            // 32 col tiles
#define KC      32                      // K chunk (bf16)
#define NKCH    (DIMN / KC)             // 8
#define PITCH   80                      // smem row pitch bytes (64 data + 16 pad)
#define SHIFT   20.0f

// ---------------- device scratch (no allocs allowed) ----------------
__device__ __nv_bfloat16 g_hi[BATCH * DIMN];
__device__ __nv_bfloat16 g_lo[BATCH * DIMN];
__device__ float g_norm[BATCH];
__device__ float g_Spart[NJT * BATCH];
__device__ float g_LSE[BATCH];
__device__ float g_pairsum[NBLK];

__constant__ int c_pa[PPB] = {0,0,0,0,0,0,0,1,1,1,1,1,1,2,2,2,2,2,3,3,3,3,4,4,4,5,5,6};
__constant__ int c_pb[PPB] = {1,2,3,4,5,6,7,2,3,4,5,6,7,3,4,5,6,7,4,5,6,7,5,6,7,6,7,7};

// ---------------- helpers ----------------
__device__ __forceinline__ uint32_t smem_u32(const void* p) {
    uint32_t a;
    asm("{ .reg .u64 t; cvta.to.shared.u64 t, %1; cvt.u32.u64 %0, t; }" : "=r"(a) : "l"(p));
    return a;
}
__device__ __forceinline__ void ldsm4(uint32_t* r, uint32_t addr) {
    asm volatile("ldmatrix.sync.aligned.m8n8.x4.shared.b16 {%0,%1,%2,%3}, [%4];"
        : "=r"(r[0]), "=r"(r[1]), "=r"(r[2]), "=r"(r[3]) : "r"(addr));
}
__device__ __forceinline__ void mma_bf16(float* c, const uint32_t* a,
                                         uint32_t b0, uint32_t b1) {
    asm volatile("mma.sync.aligned.m16n8k16.row.col.f32.bf16.bf16.f32 "
        "{%0,%1,%2,%3}, {%4,%5,%6,%7}, {%8,%9}, {%0,%1,%2,%3};"
        : "+f"(c[0]), "+f"(c[1]), "+f"(c[2]), "+f"(c[3])
        : "r"(a[0]), "r"(a[1]), "r"(a[2]), "r"(a[3]), "r"(b0), "r"(b1));
}

// ---------------------------------------------------------------------------
// K1: squared row norms (fp32, exact)
// ---------------------------------------------------------------------------
__global__ void norms_kernel(const float* __restrict__ x) {
    int warp = threadIdx.x >> 5, lane = threadIdx.x & 31;
    int row  = blockIdx.x * 8 + warp;
    const float4* xr = (const float4*)(x + (size_t)row * DIMN);
    float4 a = xr[lane * 2], b = xr[lane * 2 + 1];
    float s = a.x*a.x + a.y*a.y + a.z*a.z + a.w*a.w
            + b.x*b.x + b.y*b.y + b.z*b.z + b.w*b.w;
    #pragma unroll
    for (int o = 16; o; o >>= 1) s += __shfl_down_sync(0xffffffffu, s, o);
    if (lane == 0) g_norm[row] = s;
}

// ---------------------------------------------------------------------------
// K2: hi/lo bf16 split of x
// ---------------------------------------------------------------------------
__global__ void cvt_kernel(const float* __restrict__ x) {
    int i = blockIdx.x * blockDim.x + threadIdx.x;   // one float4
    float4 v = ((const float4*)x)[i];
    __nv_bfloat16 h0 = __float2bfloat16(v.x), h1 = __float2bfloat16(v.y);
    __nv_bfloat16 h2 = __float2bfloat16(v.z), h3 = __float2bfloat16(v.w);
    __nv_bfloat16 l0 = __float2bfloat16(v.x - __bfloat162float(h0));
    __nv_bfloat16 l1 = __float2bfloat16(v.y - __bfloat162float(h1));
    __nv_bfloat16 l2 = __float2bfloat16(v.z - __bfloat162float(h2));
    __nv_bfloat16 l3 = __float2bfloat16(v.w - __bfloat162float(h3));
    __nv_bfloat162* ph = (__nv_bfloat162*)g_hi;
    __nv_bfloat162* pl = (__nv_bfloat162*)g_lo;
    ph[i*2]   = __nv_bfloat162(h0, h1);
    ph[i*2+1] = __nv_bfloat162(h2, h3);
    pl[i*2]   = __nv_bfloat162(l0, l1);
    pl[i*2+1] = __nv_bfloat162(l2, l3);
}

// ---------------------------------------------------------------------------
// K3: Gram 128x128 tile via mma.sync bf16 (3-product split) + fused
//     distance/exp/mask/row-sum epilogue. grid (32, 32), 256 threads.
//     Warp layout: 4 row-warps x 2 col-warps; warp tile 32x64.
// ---------------------------------------------------------------------------
__global__ void __launch_bounds__(256) gram_kernel() {
    __shared__ uint8_t sAhi[MT * PITCH];
    __shared__ uint8_t sAlo[MT * PITCH];
    __shared__ uint8_t sBhi[NT * PITCH];
    __shared__ uint8_t sBlo[NT * PITCH];
    __shared__ float   norms_c[NT];
    __shared__ float   norms_r[MT];
    __shared__ float   red[MT][2];

    const int tid  = threadIdx.x;
    const int wid  = tid >> 5, lane = tid & 31;
    const int wr   = wid >> 1;            // 0..3 row-warp
    const int wc   = wid & 1;             // 0..1 col-warp
    const int rowBase = blockIdx.y * MT;
    const int colBase = blockIdx.x * NT;

    if (tid < 128) norms_c[tid] = g_norm[colBase + tid];
    else           norms_r[tid - 128] = g_norm[rowBase + tid - 128];

    const uint32_t aHi = smem_u32(sAhi), aLo = smem_u32(sAlo);
    const uint32_t bHi = smem_u32(sBhi), bLo = smem_u32(sBlo);

    float acc[2][8][4];
    #pragma unroll
    for (int mf = 0; mf < 2; mf++)
        #pragma unroll
        for (int nf = 0; nf < 8; nf++)
            #pragma unroll
            for (int e = 0; e < 4; e++) acc[mf][nf][e] = 0.f;

    // gmem load coords: thread handles 2 uint4 per tile per chunk
    const int r0 = tid >> 2;              // rows 0..63
    const int q0 = tid & 3;               // 16B quad 0..3

    for (int kc = 0; kc < NKCH; kc++) {
        if (kc > 0) __syncthreads();      // protect smem reuse
        const size_t gk = (size_t)kc * KC;
        #pragma unroll
        for (int half = 0; half < 2; half++) {
            const int r = r0 + half * 64;
            const uint32_t so = (uint32_t)(r * PITCH + q0 * 16);
            *(uint4*)(sAhi + so) = *(const uint4*)(g_hi + (size_t)(rowBase + r) * DIMN + gk + q0 * 8);
            *(uint4*)(sAlo + so) = *(const uint4*)(g_lo + (size_t)(rowBase + r) * DIMN + gk + q0 * 8);
            *(uint4*)(sBhi + so) = *(const uint4*)(g_hi + (size_t)(colBase + r) * DIMN + gk + q0 * 8);
            *(uint4*)(sBlo + so) = *(const uint4*)(g_lo + (size_t)(colBase + r) * DIMN + gk + q0 * 8);
        }
        __syncthreads();

        #pragma unroll
        for (int ks = 0; ks < 2; ks++) {
            const uint32_t koff = (uint32_t)(ks * 32 + (lane >> 4) * 16);
            uint32_t ahi[2][4], alo[2][4], bh[4][4], bl[4][4];
            #pragma unroll
            for (int mf = 0; mf < 2; mf++) {
                uint32_t ro = (uint32_t)((wr * 32 + mf * 16 + (lane & 15)) * PITCH) + koff;
                ldsm4(ahi[mf], aHi + ro);
                ldsm4(alo[mf], aLo + ro);
            }
            #pragma unroll
            for (int np = 0; np < 4; np++) {
                uint32_t co = (uint32_t)((wc * 64 + np * 16 + (lane & 15)) * PITCH) + koff;
                ldsm4(bh[np], bHi + co);
                ldsm4(bl[np], bLo + co);
            }
            #pragma unroll
            for (int mf = 0; mf < 2; mf++) {
                #pragma unroll
                for (int nf = 0; nf < 8; nf++) {
                    const int np = nf >> 1, w = nf & 1;
                    mma_bf16(acc[mf][nf], ahi[mf], bh[np][w], bh[np][w + 2]);
                    mma_bf16(acc[mf][nf], ahi[mf], bl[np][w], bl[np][w + 2]);
                    mma_bf16(acc[mf][nf], alo[mf], bh[np][w], bh[np][w + 2]);
                }
            }
        }
    }

    // ---- epilogue: d2 -> d -> exp, mask in-block cols, row sums ----
    #pragma unroll
    for (int mf = 0; mf < 2; mf++) {
        #pragma unroll
        for (int h = 0; h < 2; h++) {
            const int lr = wr * 32 + mf * 16 + (lane >> 2) + h * 8;
            const int gr = rowBase + lr;
            const float ni = norms_r[lr];
            const int rb = gr >> 3;
            float s = 0.f;
            #pragma unroll
            for (int nf = 0; nf < 8; nf++) {
                const int lc = wc * 64 + nf * 8 + (lane & 3) * 2;
                #pragma unroll
                for (int e = 0; e < 2; e++) {
                    float dot = acc[mf][nf][h * 2 + e];
                    int gc = colBase + lc + e;
                    float d2 = ni + norms_c[lc + e] - 2.0f * dot;
                    float d  = sqrtf(fmaxf(d2, 0.0f));
                    float ex = __expf(d - SHIFT);
                    s += ((gc >> 3) == rb) ? 0.0f : ex;
                }
            }
            s += __shfl_xor_sync(0xffffffffu, s, 1);
            s += __shfl_xor_sync(0xffffffffu, s, 2);
            if ((lane & 3) == 0) red[lr][wc] = s;
        }
    }
    __syncthreads();
    if (tid < MT)
        g_Spart[(size_t)blockIdx.x * BATCH + rowBase + tid] = red[tid][0] + red[tid][1];
}

// ---------------------------------------------------------------------------
// K4: per-row LSE
// ---------------------------------------------------------------------------
__global__ void lse_kernel() {
    int r = blockIdx.x * blockDim.x + threadIdx.x;
    float s = 0.f;
    #pragma unroll
    for (int jt = 0; jt < NJT; jt++) s += g_Spart[(size_t)jt * BATCH + r];
    g_LSE[r] = logf(s) + SHIFT;
}

// ---------------------------------------------------------------------------
// K5: per-8-block pair losses (exact fp32 dots from x)
// ---------------------------------------------------------------------------
__global__ void __launch_bounds__(256) pair_kernel(const float* __restrict__ x) {
    __shared__ float xs[FPC_ * DIMN];
    __shared__ float pl[PPB];
    const int blk = blockIdx.x, tid = threadIdx.x;
    const float4* src = (const float4*)(x + (size_t)blk * FPC_ * DIMN);
    float4* dst = (float4*)xs;
    dst[tid] = src[tid]; dst[tid + 256] = src[tid + 256];
    __syncthreads();

    const int warp = tid >> 5, lane = tid & 31;
    for (int p = warp; p < PPB; p += 8) {
        const int a = c_pa[p], b = c_pb[p];
        const float* xa = xs + a * DIMN;
        const float* xb = xs + b * DIMN;
        float dot = 0.f;
        #pragma unroll
        for (int k = 0; k < DIMN / 32; k++)
            dot += xa[lane + 32 * k] * xb[lane + 32 * k];
        #pragma unroll
        for (int o = 16; o; o >>= 1) dot += __shfl_down_sync(0xffffffffu, dot, o);
        if (lane == 0) {
            int ga = blk * FPC_ + a, gb = blk * FPC_ + b;
            float d2 = g_norm[ga] + g_norm[gb] - 2.0f * dot;
            float d  = sqrtf(fmaxf(d2, 0.0f));
            float z  = g_LSE[ga] - d;
            pl[p] = (z > 20.0f) ? z : log1pf(expf(z));
        }
    }
    __syncthreads();
    if (tid == 0) {
        float s = 0.f;
        #pragma unroll
        for (int p = 0; p < PPB; p++) s += pl[p];
        g_pairsum[blk] = s;
    }
}

// ---------------------------------------------------------------------------
// K6: final mean
// ---------------------------------------------------------------------------
__global__ void final_kernel(float* __restrict__ out) {
    __shared__ float sm[NBLK];
    sm[threadIdx.x] = g_pairsum[threadIdx.x];
    __syncthreads();
    #pragma unroll
    for (int s = NBLK / 2; s > 0; s >>= 1) {
        if (threadIdx.x < s) sm[threadIdx.x] += sm[threadIdx.x + s];
        __syncthreads();
    }
    if (threadIdx.x == 0) out[0] = sm[0] / (float)NPAIRS;
}

// ---------------------------------------------------------------------------
extern "C" void kernel_launch(void* const* d_in, const int* in_sizes, int n_in,
                              void* d_out, int out_size) {
    const float* x = (const float*)d_in[0];
    float* out = (float*)d_out;

    norms_kernel<<<BATCH / 8, 256>>>(x);
    cvt_kernel<<<BATCH * DIMN / 4 / 256, 256>>>(x);
    gram_kernel<<<dim3(NJT, BATCH / MT), 256>>>();
    lse_kernel<<<BATCH / 256, 256>>>();
    pair_kernel<<<NBLK, 256>>>(x);
    final_kernel<<<1, NBLK>>>(out);
}

// round 9
// speedup vs baseline: 6.3859x; 1.9017x over previous
#include <cuda_runtime.h>
#include <cuda_bf16.h>
#include <cstdint>
#include <math.h>

#define BATCH   4096
#define DIMN    256
#define FPC_    8
#define NBLK    (BATCH / FPC_)          // 512
#define PPB     28
#define NPAIRS  (NBLK * PPB)            // 14336
#define MT      128
#define NT      128
#define NJT     (BATCH / NT)            // 32 tile-blocks
#define NTILES  (NJT * (NJT + 1) / 2)   // 528 upper-tri tiles
#define KC      32                      // K chunk (bf16)
#define NKCH    (DIMN / KC)             // 8
#define PITCH   80                      // smem row pitch bytes (64 data + 16 pad)
#define SHIFT   20.0f

// ---------------- device scratch (no allocs allowed) ----------------
__device__ __nv_bfloat16 g_hi[BATCH * DIMN];
__device__ __nv_bfloat16 g_lo[BATCH * DIMN];
__device__ float g_norm[BATCH];
__device__ float g_Spart[NJT * BATCH];
__device__ float g_LSE[BATCH];
__device__ float g_pairsum[NBLK];

__constant__ int c_pa[PPB] = {0,0,0,0,0,0,0,1,1,1,1,1,1,2,2,2,2,2,3,3,3,3,4,4,4,5,5,6};
__constant__ int c_pb[PPB] = {1,2,3,4,5,6,7,2,3,4,5,6,7,3,4,5,6,7,4,5,6,7,5,6,7,6,7,7};

// ---------------- helpers ----------------
__device__ __forceinline__ uint32_t smem_u32(const void* p) {
    uint32_t a;
    asm("{ .reg .u64 t; cvta.to.shared.u64 t, %1; cvt.u32.u64 %0, t; }" : "=r"(a) : "l"(p));
    return a;
}
__device__ __forceinline__ void ldsm4(uint32_t* r, uint32_t addr) {
    asm volatile("ldmatrix.sync.aligned.m8n8.x4.shared.b16 {%0,%1,%2,%3}, [%4];"
        : "=r"(r[0]), "=r"(r[1]), "=r"(r[2]), "=r"(r[3]) : "r"(addr));
}
__device__ __forceinline__ void mma_bf16(float* c, const uint32_t* a,
                                         uint32_t b0, uint32_t b1) {
    asm volatile("mma.sync.aligned.m16n8k16.row.col.f32.bf16.bf16.f32 "
        "{%0,%1,%2,%3}, {%4,%5,%6,%7}, {%8,%9}, {%0,%1,%2,%3};"
        : "+f"(c[0]), "+f"(c[1]), "+f"(c[2]), "+f"(c[3])
        : "r"(a[0]), "r"(a[1]), "r"(a[2]), "r"(a[3]), "r"(b0), "r"(b1));
}

// ---------------------------------------------------------------------------
// K1: squared row norms (fp32, exact)
// ---------------------------------------------------------------------------
__global__ void norms_kernel(const float* __restrict__ x) {
    int warp = threadIdx.x >> 5, lane = threadIdx.x & 31;
    int row  = blockIdx.x * 8 + warp;
    const float4* xr = (const float4*)(x + (size_t)row * DIMN);
    float4 a = xr[lane * 2], b = xr[lane * 2 + 1];
    float s = a.x*a.x + a.y*a.y + a.z*a.z + a.w*a.w
            + b.x*b.x + b.y*b.y + b.z*b.z + b.w*b.w;
    #pragma unroll
    for (int o = 16; o; o >>= 1) s += __shfl_down_sync(0xffffffffu, s, o);
    if (lane == 0) g_norm[row] = s;
}

// ---------------------------------------------------------------------------
// K2: hi/lo bf16 split of x
// ---------------------------------------------------------------------------
__global__ void cvt_kernel(const float* __restrict__ x) {
    int i = blockIdx.x * blockDim.x + threadIdx.x;   // one float4
    float4 v = ((const float4*)x)[i];
    __nv_bfloat16 h0 = __float2bfloat16(v.x), h1 = __float2bfloat16(v.y);
    __nv_bfloat16 h2 = __float2bfloat16(v.z), h3 = __float2bfloat16(v.w);
    __nv_bfloat16 l0 = __float2bfloat16(v.x - __bfloat162float(h0));
    __nv_bfloat16 l1 = __float2bfloat16(v.y - __bfloat162float(h1));
    __nv_bfloat16 l2 = __float2bfloat16(v.z - __bfloat162float(h2));
    __nv_bfloat16 l3 = __float2bfloat16(v.w - __bfloat162float(h3));
    __nv_bfloat162* ph = (__nv_bfloat162*)g_hi;
    __nv_bfloat162* pl = (__nv_bfloat162*)g_lo;
    ph[i*2]   = __nv_bfloat162(h0, h1);
    ph[i*2+1] = __nv_bfloat162(h2, h3);
    pl[i*2]   = __nv_bfloat162(l0, l1);
    pl[i*2+1] = __nv_bfloat162(l2, l3);
}

// ---------------------------------------------------------------------------
// K3: symmetric Gram — only upper-triangle tiles (I <= J), 528 CTAs.
//     Off-diagonal tiles emit BOTH row sums (slot J, rows of I) and, by
//     symmetry, column sums (slot I, rows of J). Diagonal tiles emit row
//     sums with the in-8-block mask.
// ---------------------------------------------------------------------------
__global__ void __launch_bounds__(256) gram_kernel() {
    __shared__ uint8_t sAhi[MT * PITCH];
    __shared__ uint8_t sAlo[MT * PITCH];
    __shared__ uint8_t sBhi[NT * PITCH];
    __shared__ uint8_t sBlo[NT * PITCH];
    __shared__ float   norms_c[NT];
    __shared__ float   norms_r[MT];
    __shared__ float   red_r[MT][2];
    __shared__ float   red_c[NT][4];

    // decode linear tile id -> (I, J) with I <= J
    int k = blockIdx.x;
    int J = (int)((sqrtf(8.0f * (float)k + 1.0f) - 1.0f) * 0.5f);
    while ((J + 1) * (J + 2) / 2 <= k) J++;
    while (J * (J + 1) / 2 > k) J--;
    int I = k - J * (J + 1) / 2;

    const int tid  = threadIdx.x;
    const int wid  = tid >> 5, lane = tid & 31;
    const int wr   = wid >> 1;            // 0..3 row-warp
    const int wc   = wid & 1;             // 0..1 col-warp
    const int rowBase = I * MT;
    const int colBase = J * NT;
    const bool isDiag = (I == J);

    if (tid < 128) norms_c[tid] = g_norm[colBase + tid];
    else           norms_r[tid - 128] = g_norm[rowBase + tid - 128];

    const uint32_t aHi = smem_u32(sAhi), aLo = smem_u32(sAlo);
    const uint32_t bHi = smem_u32(sBhi), bLo = smem_u32(sBlo);

    float acc[2][8][4];
    #pragma unroll
    for (int mf = 0; mf < 2; mf++)
        #pragma unroll
        for (int nf = 0; nf < 8; nf++)
            #pragma unroll
            for (int e = 0; e < 4; e++) acc[mf][nf][e] = 0.f;

    const int r0 = tid >> 2;              // rows 0..63
    const int q0 = tid & 3;               // 16B quad

    for (int kc = 0; kc < NKCH; kc++) {
        if (kc > 0) __syncthreads();
        const size_t gk = (size_t)kc * KC;
        #pragma unroll
        for (int half = 0; half < 2; half++) {
            const int r = r0 + half * 64;
            const uint32_t so = (uint32_t)(r * PITCH + q0 * 16);
            *(uint4*)(sAhi + so) = *(const uint4*)(g_hi + (size_t)(rowBase + r) * DIMN + gk + q0 * 8);
            *(uint4*)(sAlo + so) = *(const uint4*)(g_lo + (size_t)(rowBase + r) * DIMN + gk + q0 * 8);
            *(uint4*)(sBhi + so) = *(const uint4*)(g_hi + (size_t)(colBase + r) * DIMN + gk + q0 * 8);
            *(uint4*)(sBlo + so) = *(const uint4*)(g_lo + (size_t)(colBase + r) * DIMN + gk + q0 * 8);
        }
        __syncthreads();

        #pragma unroll
        for (int ks = 0; ks < 2; ks++) {
            const uint32_t koff = (uint32_t)(ks * 32 + (lane >> 4) * 16);
            uint32_t ahi[2][4], alo[2][4], bh[4][4], bl[4][4];
            #pragma unroll
            for (int mf = 0; mf < 2; mf++) {
                uint32_t ro = (uint32_t)((wr * 32 + mf * 16 + (lane & 15)) * PITCH) + koff;
                ldsm4(ahi[mf], aHi + ro);
                ldsm4(alo[mf], aLo + ro);
            }
            #pragma unroll
            for (int np = 0; np < 4; np++) {
                uint32_t co = (uint32_t)((wc * 64 + np * 16 + (lane & 15)) * PITCH) + koff;
                ldsm4(bh[np], bHi + co);
                ldsm4(bl[np], bLo + co);
            }
            #pragma unroll
            for (int mf = 0; mf < 2; mf++) {
                #pragma unroll
                for (int nf = 0; nf < 8; nf++) {
                    const int np = nf >> 1, w = nf & 1;
                    mma_bf16(acc[mf][nf], ahi[mf], bh[np][w], bh[np][w + 2]);
                    mma_bf16(acc[mf][nf], ahi[mf], bl[np][w], bl[np][w + 2]);
                    mma_bf16(acc[mf][nf], alo[mf], bh[np][w], bh[np][w + 2]);
                }
            }
        }
    }

    // ---- epilogue: d2 -> d -> exp; row sums + (off-diag) col sums ----
    float colsum[16];
    #pragma unroll
    for (int i = 0; i < 16; i++) colsum[i] = 0.f;

    #pragma unroll
    for (int mf = 0; mf < 2; mf++) {
        #pragma unroll
        for (int h = 0; h < 2; h++) {
            const int lr = wr * 32 + mf * 16 + (lane >> 2) + h * 8;
            const int gr = rowBase + lr;
            const float ni = norms_r[lr];
            const int rb = gr >> 3;
            float s = 0.f;
            #pragma unroll
            for (int nf = 0; nf < 8; nf++) {
                const int lc = wc * 64 + nf * 8 + (lane & 3) * 2;
                #pragma unroll
                for (int e = 0; e < 2; e++) {
                    float dot = acc[mf][nf][h * 2 + e];
                    int gc = colBase + lc + e;
                    float d2 = ni + norms_c[lc + e] - 2.0f * dot;
                    float d  = sqrtf(fmaxf(d2, 0.0f));
                    float ex = __expf(d - SHIFT);
                    if (isDiag && ((gc >> 3) == rb)) ex = 0.f;
                    s += ex;
                    colsum[nf * 2 + e] += ex;
                }
            }
            s += __shfl_xor_sync(0xffffffffu, s, 1);
            s += __shfl_xor_sync(0xffffffffu, s, 2);
            if ((lane & 3) == 0) red_r[lr][wc] = s;
        }
    }

    if (!isDiag) {
        #pragma unroll
        for (int i = 0; i < 16; i++) {
            colsum[i] += __shfl_xor_sync(0xffffffffu, colsum[i], 4);
            colsum[i] += __shfl_xor_sync(0xffffffffu, colsum[i], 8);
            colsum[i] += __shfl_xor_sync(0xffffffffu, colsum[i], 16);
        }
        if (lane < 4) {
            #pragma unroll
            for (int nf = 0; nf < 8; nf++)
                #pragma unroll
                for (int e = 0; e < 2; e++)
                    red_c[wc * 64 + nf * 8 + lane * 2 + e][wr] = colsum[nf * 2 + e];
        }
    }
    __syncthreads();

    if (tid < MT) {
        g_Spart[(size_t)J * BATCH + rowBase + tid] = red_r[tid][0] + red_r[tid][1];
        if (!isDiag)
            g_Spart[(size_t)I * BATCH + colBase + tid] =
                red_c[tid][0] + red_c[tid][1] + red_c[tid][2] + red_c[tid][3];
    }
}

// ---------------------------------------------------------------------------
// K4: per-row LSE
// ---------------------------------------------------------------------------
__global__ void lse_kernel() {
    int r = blockIdx.x * blockDim.x + threadIdx.x;
    float s = 0.f;
    #pragma unroll
    for (int jt = 0; jt < NJT; jt++) s += g_Spart[(size_t)jt * BATCH + r];
    g_LSE[r] = logf(s) + SHIFT;
}

// ---------------------------------------------------------------------------
// K5: per-8-block pair losses (exact fp32 dots from x)
// ---------------------------------------------------------------------------
__global__ void __launch_bounds__(256) pair_kernel(const float* __restrict__ x) {
    __shared__ float xs[FPC_ * DIMN];
    __shared__ float pl[PPB];
    const int blk = blockIdx.x, tid = threadIdx.x;
    const float4* src = (const float4*)(x + (size_t)blk * FPC_ * DIMN);
    float4* dst = (float4*)xs;
    dst[tid] = src[tid]; dst[tid + 256] = src[tid + 256];
    __syncthreads();

    const int warp = tid >> 5, lane = tid & 31;
    for (int p = warp; p < PPB; p += 8) {
        const int a = c_pa[p], b = c_pb[p];
        const float* xa = xs + a * DIMN;
        const float* xb = xs + b * DIMN;
        float dot = 0.f;
        #pragma unroll
        for (int k = 0; k < DIMN / 32; k++)
            dot += xa[lane + 32 * k] * xb[lane + 32 * k];
        #pragma unroll
        for (int o = 16; o; o >>= 1) dot += __shfl_down_sync(0xffffffffu, dot, o);
        if (lane == 0) {
            int ga = blk * FPC_ + a, gb = blk * FPC_ + b;
            float d2 = g_norm[ga] + g_norm[gb] - 2.0f * dot;
            float d  = sqrtf(fmaxf(d2, 0.0f));
            float z  = g_LSE[ga] - d;
            pl[p] = (z > 20.0f) ? z : log1pf(expf(z));
        }
    }
    __syncthreads();
    if (tid == 0) {
        float s = 0.f;
        #pragma unroll
        for (int p = 0; p < PPB; p++) s += pl[p];
        g_pairsum[blk] = s;
    }
}

// ---------------------------------------------------------------------------
// K6: final mean
// ---------------------------------------------------------------------------
__global__ void final_kernel(float* __restrict__ out) {
    __shared__ float sm[NBLK];
    sm[threadIdx.x] = g_pairsum[threadIdx.x];
    __syncthreads();
    #pragma unroll
    for (int s = NBLK / 2; s > 0; s >>= 1) {
        if (threadIdx.x < s) sm[threadIdx.x] += sm[threadIdx.x + s];
        __syncthreads();
    }
    if (threadIdx.x == 0) out[0] = sm[0] / (float)NPAIRS;
}

// ---------------------------------------------------------------------------
extern "C" void kernel_launch(void* const* d_in, const int* in_sizes, int n_in,
                              void* d_out, int out_size) {
    const float* x = (const float*)d_in[0];
    float* out = (float*)d_out;

    norms_kernel<<<BATCH / 8, 256>>>(x);
    cvt_kernel<<<BATCH * DIMN / 4 / 256, 256>>>(x);
    gram_kernel<<<NTILES, 256>>>();
    lse_kernel<<<BATCH / 256, 256>>>();
    pair_kernel<<<NBLK, 256>>>(x);
    final_kernel<<<1, NBLK>>>(out);
}